// round 9
// baseline (speedup 1.0000x reference)
#include <cuda_runtime.h>
#include <cstdint>

// EmbedMeanField (structure2vec) for GB300 — CSR "pull" dataflow.
// Sizes fixed by dataset: N=50000, E=800000, G=128, FN=64, FE=16, D=64, LV=3.
//
// Per launch:
//  A. Build CSR over edge_dst on-device:
//     zero deg -> histogram -> 3-kernel exclusive scan -> fill (csr_src, csr_eid)
//  B. k_input: efsum_n = sum_{e->n} ef[e]  (pulled, raw features);
//     im = nf@Wn + bn + efsum_n@We + deg*be ; h = relu(im)
//     (uses linearity: segment_sum(ef@We) == segment_sum(ef)@We)
//  C. LV-1 x k_level: pool_n = sum h[src] (registers, unrolled x4 gather);
//     h' = relu(pool@Wc+bc+im)   (double-buffered g_h <-> g_h2)
//  D. k_level_final: gather+combine, then o = relu(h@Wf+bf), out[gid] += o.
//
// Audited invariants:
//  - dir chain (LV=3): lv0 h->h2, lv1 h2->h, final reads g_h (dir=0).
//  - deg-0 nodes: im = nf@Wn + bn only; correct (no edge contributions).
//  - scan capacity: nsb = ceil(N/512) = 98 <= 256 (g_blk bound).
//  - all launches default-stream, no sync/alloc -> graph-capturable.
//  - im loads hoisted before the shuffle GEMV (latency overlap).
//  - gathers via __ldg (hin strictly read-only within each kernel).

#define D    64
#define FE   16
#define MAXN 50000
#define MAXE 800000
#define SCAN_B 512

// scratch (static __device__; allocation-free per harness rules)
__device__ __align__(256) float g_im [(size_t)MAXN * D];
__device__ __align__(256) float g_h  [(size_t)MAXN * D];
__device__ __align__(256) float g_h2 [(size_t)MAXN * D];
__device__ int g_deg   [MAXN];
__device__ int g_rptr  [MAXN];
__device__ int g_cursor[MAXN];
__device__ int g_blk   [256];
__device__ int g_csrc  [MAXE];   // src node per CSR slot
__device__ int g_ceid  [MAXE];   // edge id per CSR slot

// ------------------------------------------------------------- CSR build
__global__ void k_zero_deg(int N) {
    int i = blockIdx.x * blockDim.x + threadIdx.x;
    if (i < N) g_deg[i] = 0;
}
__global__ void k_hist(const int* __restrict__ edst, int E) {
    int e = blockIdx.x * blockDim.x + threadIdx.x;
    if (e < E) atomicAdd(&g_deg[edst[e]], 1);
}
// block-local inclusive scan (Hillis–Steele); exclusive result to g_rptr,
// block totals to g_blk.
__global__ void k_scanA(int N) {
    __shared__ int s[SCAN_B];
    int i = blockIdx.x * SCAN_B + threadIdx.x;
    int v = (i < N) ? g_deg[i] : 0;
    s[threadIdx.x] = v;
    __syncthreads();
    #pragma unroll
    for (int off = 1; off < SCAN_B; off <<= 1) {
        int t = (threadIdx.x >= off) ? s[threadIdx.x - off] : 0;
        __syncthreads();
        s[threadIdx.x] += t;
        __syncthreads();
    }
    if (i < N) g_rptr[i] = s[threadIdx.x] - v;          // exclusive within block
    if (threadIdx.x == SCAN_B - 1) g_blk[blockIdx.x] = s[SCAN_B - 1];
}
// serial scan of <=256 block totals (98 for N=50000); negligible cost.
__global__ void k_scanB(int nb) {
    if (threadIdx.x == 0 && blockIdx.x == 0) {
        int run = 0;
        for (int i = 0; i < nb; i++) { int v = g_blk[i]; g_blk[i] = run; run += v; }
    }
}
__global__ void k_scanC(int N) {
    int i = blockIdx.x * blockDim.x + threadIdx.x;
    if (i < N) {
        int v = g_rptr[i] + g_blk[i / SCAN_B];
        g_rptr[i]   = v;
        g_cursor[i] = v;
    }
}
__global__ void k_fill(const int* __restrict__ esrc,
                       const int* __restrict__ edst, int E) {
    int e = blockIdx.x * blockDim.x + threadIdx.x;
    if (e < E) {
        int d = edst[e];
        int p = atomicAdd(&g_cursor[d], 1);
        g_csrc[p] = esrc[e];
        g_ceid[p] = e;
    }
}

__global__ void k_zero_out(float* __restrict__ p, int n) {
    int i = blockIdx.x * blockDim.x + threadIdx.x;
    if (i < n) p[i] = 0.f;
}

// ------- B: fused input layer ------------------------------------------------
// Warp per node; lane owns cols {lane, lane+32}.
// Edge layer uses linearity: sum_e(ef[e] @ We) = (sum_e ef[e]) @ We.
__global__ void k_input(const float* __restrict__ nf,  // [N][64]
                        const float* __restrict__ ef,  // [E][16]
                        const float* __restrict__ Wn,  // [64][64]
                        const float* __restrict__ bn,  // [64]
                        const float* __restrict__ We,  // [16][64]
                        const float* __restrict__ be,  // [64]
                        int N) {
    __shared__ float Wns[D][D];
    __shared__ float Wes[FE][D];
    __shared__ float bns[D], bes[D];
    int tid = threadIdx.x;
    for (int i = tid; i < D * D; i += blockDim.x) Wns[i / D][i % D] = Wn[i];
    for (int i = tid; i < FE * D; i += blockDim.x) Wes[i / D][i % D] = We[i];
    if (tid < D) { bns[tid] = bn[tid]; bes[tid] = be[tid]; }
    __syncthreads();

    int lane = tid & 31;
    int wpb  = blockDim.x >> 5;
    for (int n = blockIdx.x * wpb + (tid >> 5); n < N; n += gridDim.x * wpb) {
        // node linear
        const float* row = nf + (size_t)n * D;
        float p0 = row[lane], p1 = row[lane + 32];
        float a0 = 0.f, a1 = 0.f;
        #pragma unroll
        for (int k = 0; k < 32; k++) {
            float v = __shfl_sync(0xffffffffu, p0, k);
            a0 = fmaf(v, Wns[k][lane], a0);
            a1 = fmaf(v, Wns[k][lane + 32], a1);
        }
        #pragma unroll
        for (int k = 0; k < 32; k++) {
            float v = __shfl_sync(0xffffffffu, p1, k);
            a0 = fmaf(v, Wns[k + 32][lane], a0);
            a1 = fmaf(v, Wns[k + 32][lane + 32], a1);
        }
        // accumulate raw edge features of incoming edges (lanes 0..15 active;
        // shuffles stay outside the conditional -> convergent)
        int start = g_rptr[n];
        int dg    = g_deg[n];
        int end   = start + dg;
        float fs = 0.f;
        if (lane < FE) {
            int i = start;
            for (; i + 3 < end; i += 4) {
                int e0 = g_ceid[i],     e1 = g_ceid[i + 1];
                int e2 = g_ceid[i + 2], e3 = g_ceid[i + 3];
                float v0 = __ldg(&ef[(size_t)e0 * FE + lane]);
                float v1 = __ldg(&ef[(size_t)e1 * FE + lane]);
                float v2 = __ldg(&ef[(size_t)e2 * FE + lane]);
                float v3 = __ldg(&ef[(size_t)e3 * FE + lane]);
                fs += (v0 + v1) + (v2 + v3);
            }
            for (; i < end; i++)
                fs += __ldg(&ef[(size_t)g_ceid[i] * FE + lane]);
        }
        // one edge-GEMV on the summed features
        #pragma unroll
        for (int k = 0; k < FE; k++) {
            float v = __shfl_sync(0xffffffffu, fs, k);
            a0 = fmaf(v, Wes[k][lane], a0);
            a1 = fmaf(v, Wes[k][lane + 32], a1);
        }
        // bias: bn once + be per incoming edge (deg times)
        float fd = (float)dg;
        float im0 = a0 + bns[lane]      + fd * bes[lane];
        float im1 = a1 + bns[lane + 32] + fd * bes[lane + 32];
        size_t o = (size_t)n * D;
        g_im[o + lane]      = im0;
        g_im[o + lane + 32] = im1;
        g_h[o + lane]       = fmaxf(im0, 0.f);
        g_h[o + lane + 32]  = fmaxf(im1, 0.f);
    }
}

// ------- C: mean-field level: pull-gather (x4 unrolled) + combine ------------
// dir=0: read g_h  -> write g_h2 ; dir=1: read g_h2 -> write g_h
__global__ void k_level(const float* __restrict__ W,   // [64][64]
                        const float* __restrict__ b,   // [64]
                        int dir, int N) {
    __shared__ float Ws[D][D];
    __shared__ float bs[D];
    int tid = threadIdx.x;
    for (int i = tid; i < D * D; i += blockDim.x) Ws[i / D][i % D] = W[i];
    if (tid < D) bs[tid] = b[tid];
    __syncthreads();

    const float* hin  = dir ? g_h2 : g_h;
    float*       hout = dir ? g_h  : g_h2;

    int lane = tid & 31;
    int wpb  = blockDim.x >> 5;
    for (int n = blockIdx.x * wpb + (tid >> 5); n < N; n += gridDim.x * wpb) {
        int start = g_rptr[n];
        int end   = start + g_deg[n];
        float p0 = 0.f, p1 = 0.f;
        int i = start;
        for (; i + 3 < end; i += 4) {
            int s0 = g_csrc[i],     s1 = g_csrc[i + 1];
            int s2 = g_csrc[i + 2], s3 = g_csrc[i + 3];
            const float* r0 = hin + (size_t)s0 * D;
            const float* r1 = hin + (size_t)s1 * D;
            const float* r2 = hin + (size_t)s2 * D;
            const float* r3 = hin + (size_t)s3 * D;
            p0 += (__ldg(&r0[lane]) + __ldg(&r1[lane]))
                + (__ldg(&r2[lane]) + __ldg(&r3[lane]));
            p1 += (__ldg(&r0[lane + 32]) + __ldg(&r1[lane + 32]))
                + (__ldg(&r2[lane + 32]) + __ldg(&r3[lane + 32]));
        }
        for (; i < end; i++) {
            const float* r = hin + (size_t)g_csrc[i] * D;
            p0 += __ldg(&r[lane]);
            p1 += __ldg(&r[lane + 32]);
        }
        // issue im loads early: their L2 latency overlaps the 64-step GEMV
        size_t o = (size_t)n * D;
        float im0 = g_im[o + lane];
        float im1 = g_im[o + lane + 32];
        float a0 = 0.f, a1 = 0.f;
        #pragma unroll
        for (int k = 0; k < 32; k++) {
            float v = __shfl_sync(0xffffffffu, p0, k);
            a0 = fmaf(v, Ws[k][lane], a0);
            a1 = fmaf(v, Ws[k][lane + 32], a1);
        }
        #pragma unroll
        for (int k = 0; k < 32; k++) {
            float v = __shfl_sync(0xffffffffu, p1, k);
            a0 = fmaf(v, Ws[k + 32][lane], a0);
            a1 = fmaf(v, Ws[k + 32][lane + 32], a1);
        }
        float h0 = fmaxf(a0 + bs[lane]      + im0, 0.f);
        float h1 = fmaxf(a1 + bs[lane + 32] + im1, 0.f);
        hout[o + lane]      = h0;
        hout[o + lane + 32] = h1;
    }
}

// ------- D: final level fused: gather + combine + final proj + graph pool ----
__global__ void k_level_final(const float* __restrict__ Wc,  // [64][64]
                              const float* __restrict__ bc,  // [64]
                              const float* __restrict__ Wf,  // [64][64]
                              const float* __restrict__ bf,  // [64]
                              const int*   __restrict__ gid, // [N]
                              float*       __restrict__ out, // [G][64]
                              int dir, int N) {
    __shared__ float Wcs[D][D];
    __shared__ float Wfs[D][D];
    __shared__ float bcs[D], bfs[D];
    int tid = threadIdx.x;
    for (int i = tid; i < D * D; i += blockDim.x) {
        Wcs[i / D][i % D] = Wc[i];
        Wfs[i / D][i % D] = Wf[i];
    }
    if (tid < D) { bcs[tid] = bc[tid]; bfs[tid] = bf[tid]; }
    __syncthreads();

    const float* hin = dir ? g_h2 : g_h;

    int lane = tid & 31;
    int wpb  = blockDim.x >> 5;
    for (int n = blockIdx.x * wpb + (tid >> 5); n < N; n += gridDim.x * wpb) {
        int start = g_rptr[n];
        int end   = start + g_deg[n];
        float p0 = 0.f, p1 = 0.f;
        int i = start;
        for (; i + 3 < end; i += 4) {
            int s0 = g_csrc[i],     s1 = g_csrc[i + 1];
            int s2 = g_csrc[i + 2], s3 = g_csrc[i + 3];
            const float* r0 = hin + (size_t)s0 * D;
            const float* r1 = hin + (size_t)s1 * D;
            const float* r2 = hin + (size_t)s2 * D;
            const float* r3 = hin + (size_t)s3 * D;
            p0 += (__ldg(&r0[lane]) + __ldg(&r1[lane]))
                + (__ldg(&r2[lane]) + __ldg(&r3[lane]));
            p1 += (__ldg(&r0[lane + 32]) + __ldg(&r1[lane + 32]))
                + (__ldg(&r2[lane + 32]) + __ldg(&r3[lane + 32]));
        }
        for (; i < end; i++) {
            const float* r = hin + (size_t)g_csrc[i] * D;
            p0 += __ldg(&r[lane]);
            p1 += __ldg(&r[lane + 32]);
        }
        // early loads: im rows and graph id overlap the GEMV chains
        size_t o = (size_t)n * D;
        float im0 = g_im[o + lane];
        float im1 = g_im[o + lane + 32];
        int g = gid[n];
        float a0 = 0.f, a1 = 0.f;
        #pragma unroll
        for (int k = 0; k < 32; k++) {
            float v = __shfl_sync(0xffffffffu, p0, k);
            a0 = fmaf(v, Wcs[k][lane], a0);
            a1 = fmaf(v, Wcs[k][lane + 32], a1);
        }
        #pragma unroll
        for (int k = 0; k < 32; k++) {
            float v = __shfl_sync(0xffffffffu, p1, k);
            a0 = fmaf(v, Wcs[k + 32][lane], a0);
            a1 = fmaf(v, Wcs[k + 32][lane + 32], a1);
        }
        float h0 = fmaxf(a0 + bcs[lane]      + im0, 0.f);
        float h1 = fmaxf(a1 + bcs[lane + 32] + im1, 0.f);
        // final projection (h stays in registers)
        float f0 = 0.f, f1 = 0.f;
        #pragma unroll
        for (int k = 0; k < 32; k++) {
            float v = __shfl_sync(0xffffffffu, h0, k);
            f0 = fmaf(v, Wfs[k][lane], f0);
            f1 = fmaf(v, Wfs[k][lane + 32], f1);
        }
        #pragma unroll
        for (int k = 0; k < 32; k++) {
            float v = __shfl_sync(0xffffffffu, h1, k);
            f0 = fmaf(v, Wfs[k + 32][lane], f0);
            f1 = fmaf(v, Wfs[k + 32][lane + 32], f1);
        }
        float o0 = fmaxf(f0 + bfs[lane],      0.f);
        float o1 = fmaxf(f1 + bfs[lane + 32], 0.f);
        atomicAdd(&out[(size_t)g * D + lane],      o0);
        atomicAdd(&out[(size_t)g * D + lane + 32], o1);
    }
}

// ------------------------------------------------------------------------ host
extern "C" void kernel_launch(void* const* d_in, const int* in_sizes, int n_in,
                              void* d_out, int out_size) {
    // Disambiguate input order: dict order has edge_src/edge_dst (same size E)
    // at slots 2,3; signature order has W_n2l (4096) and b_n2l (64) there.
    bool dict = (in_sizes[2] == in_sizes[3]);
    int iNF = 0, iEF = 1, iSRC, iDST, iGID, iWn, ibn, iWe, ibe, iWc, ibc, iWf, ibf;
    if (dict) { iSRC = 2; iDST = 3; iGID = 4; iWn = 5; ibn = 6; iWe = 7; ibe = 8;
                iWc = 9; ibc = 10; iWf = 11; ibf = 12; }
    else      { iWn = 2; ibn = 3; iWe = 4; ibe = 5; iWc = 6; ibc = 7; iWf = 8;
                ibf = 9; iSRC = 10; iDST = 11; iGID = 12; }

    const float* nf   = (const float*)d_in[iNF];
    const float* ef   = (const float*)d_in[iEF];
    const int*   esrc = (const int*)  d_in[iSRC];
    const int*   edst = (const int*)  d_in[iDST];
    const int*   gid  = (const int*)  d_in[iGID];
    const float* Wn   = (const float*)d_in[iWn];
    const float* bn   = (const float*)d_in[ibn];
    const float* We   = (const float*)d_in[iWe];
    const float* be   = (const float*)d_in[ibe];
    const float* Wc   = (const float*)d_in[iWc];   // [LV][64][64]
    const float* bc   = (const float*)d_in[ibc];   // [LV][64]
    const float* Wf   = (const float*)d_in[iWf];
    const float* bf   = (const float*)d_in[ibf];
    float* out = (float*)d_out;

    int N  = in_sizes[iGID];            // graph_id has N entries
    int E  = in_sizes[iSRC];
    int LV = in_sizes[iWc] / (D * D);   // 3

    const int THR = 256;
    int nb  = (N + THR - 1) / THR;
    int ebk = (E + THR - 1) / THR;
    int nsb = (N + SCAN_B - 1) / SCAN_B;   // scan blocks (98 <= 256)
    const int GSB = 1184;                  // grid-stride blocks for node kernels

    // A. CSR build
    k_zero_deg<<<nb, THR>>>(N);
    k_hist<<<ebk, THR>>>(edst, E);
    k_scanA<<<nsb, SCAN_B>>>(N);
    k_scanB<<<1, 32>>>(nsb);
    k_scanC<<<nb, THR>>>(N);
    k_fill<<<ebk, THR>>>(esrc, edst, E);

    // B. fused input layer
    k_input<<<GSB, THR>>>(nf, ef, Wn, bn, We, be, N);

    // C. mean-field levels 0..LV-2 (double-buffered)
    int dir = 0;
    for (int lv = 0; lv < LV - 1; lv++) {
        k_level<<<GSB, THR>>>(Wc + (size_t)lv * D * D, bc + (size_t)lv * D, dir, N);
        dir ^= 1;
    }

    // D. final level fused with projection + graph pooling
    k_zero_out<<<(out_size + THR - 1) / THR, THR>>>(out, out_size);
    k_level_final<<<GSB, THR>>>(Wc + (size_t)(LV - 1) * D * D,
                                bc + (size_t)(LV - 1) * D,
                                Wf, bf, gid, out, dir, N);
}

// round 11
// speedup vs baseline: 1.0068x; 1.0068x over previous
#include <cuda_runtime.h>
#include <cstdint>

// EmbedMeanField (structure2vec) for GB300 — CSR "pull" dataflow, float2 datapath.
// N=50000, E=800000, G=128, FN=64, FE=16, D=64, LV=3.
// R9 measured 301.1us (latency-bound gathers; serial scanB 7.4us).
// R10/R11: float2 everywhere (halve LDG/STG count, 2x bytes in flight) + parallel scanB.
// Lane owns column pair {2*lane, 2*lane+1}; weights in smem as float2.

#define D    64
#define D2   32          // D/2 float2 per row
#define FE   16
#define FE2  8
#define MAXN 50000
#define MAXE 800000
#define SCAN_B 512

__device__ __align__(256) float g_im [(size_t)MAXN * D];
__device__ __align__(256) float g_h  [(size_t)MAXN * D];
__device__ __align__(256) float g_hb [(size_t)MAXN * D];
__device__ int g_deg   [MAXN];
__device__ int g_rptr  [MAXN];
__device__ int g_cursor[MAXN];
__device__ int g_blk   [256];
__device__ int g_csrc  [MAXE];
__device__ int g_ceid  [MAXE];

// ------------------------------------------------------------- CSR build
__global__ void k_zero_deg(int N) {
    int i = blockIdx.x * blockDim.x + threadIdx.x;
    if (i < N) g_deg[i] = 0;
}
__global__ void k_hist(const int* __restrict__ edst, int E) {
    int e = blockIdx.x * blockDim.x + threadIdx.x;
    if (e < E) atomicAdd(&g_deg[edst[e]], 1);
}
__global__ void k_scanA(int N) {
    __shared__ int s[SCAN_B];
    int i = blockIdx.x * SCAN_B + threadIdx.x;
    int v = (i < N) ? g_deg[i] : 0;
    s[threadIdx.x] = v;
    __syncthreads();
    #pragma unroll
    for (int off = 1; off < SCAN_B; off <<= 1) {
        int t = (threadIdx.x >= off) ? s[threadIdx.x - off] : 0;
        __syncthreads();
        s[threadIdx.x] += t;
        __syncthreads();
    }
    if (i < N) g_rptr[i] = s[threadIdx.x] - v;
    if (threadIdx.x == SCAN_B - 1) g_blk[blockIdx.x] = s[SCAN_B - 1];
}
// parallel exclusive scan of <=256 block totals (was 7.4us serial in R9)
__global__ void k_scanB(int nb) {
    __shared__ int s[256];
    int t = threadIdx.x;
    int v = (t < nb) ? g_blk[t] : 0;
    s[t] = v;
    __syncthreads();
    #pragma unroll
    for (int off = 1; off < 256; off <<= 1) {
        int u = (t >= off) ? s[t - off] : 0;
        __syncthreads();
        s[t] += u;
        __syncthreads();
    }
    if (t < nb) g_blk[t] = s[t] - v;   // exclusive
}
__global__ void k_scanC(int N) {
    int i = blockIdx.x * blockDim.x + threadIdx.x;
    if (i < N) {
        int v = g_rptr[i] + g_blk[i / SCAN_B];
        g_rptr[i]   = v;
        g_cursor[i] = v;
    }
}
__global__ void k_fill(const int* __restrict__ esrc,
                       const int* __restrict__ edst, int E) {
    int e = blockIdx.x * blockDim.x + threadIdx.x;
    if (e < E) {
        int d = edst[e];
        int p = atomicAdd(&g_cursor[d], 1);
        g_csrc[p] = esrc[e];
        g_ceid[p] = e;
    }
}
__global__ void k_zero_out(float* __restrict__ p, int n) {
    int i = blockIdx.x * blockDim.x + threadIdx.x;
    if (i < n) p[i] = 0.f;
}

// ------- B: fused input layer (float2 datapath) ------------------------------
__global__ void k_input(const float* __restrict__ nf,  // [N][64]
                        const float* __restrict__ ef,  // [E][16]
                        const float* __restrict__ Wn,  // [64][64]
                        const float* __restrict__ bn,  // [64]
                        const float* __restrict__ We,  // [16][64]
                        const float* __restrict__ be,  // [64]
                        int N) {
    __shared__ float2 Wns[D][D2];      // Wns[r][c] = {Wn[r][2c], Wn[r][2c+1]}
    __shared__ float2 Wes[FE][D2];
    __shared__ float2 bns[D2], bes[D2];
    int tid = threadIdx.x;
    for (int i = tid; i < D * D2; i += blockDim.x)
        Wns[i / D2][i % D2] = reinterpret_cast<const float2*>(Wn)[i];
    for (int i = tid; i < FE * D2; i += blockDim.x)
        Wes[i / D2][i % D2] = reinterpret_cast<const float2*>(We)[i];
    if (tid < D2) {
        bns[tid] = reinterpret_cast<const float2*>(bn)[tid];
        bes[tid] = reinterpret_cast<const float2*>(be)[tid];
    }
    __syncthreads();

    const float2* nf2 = reinterpret_cast<const float2*>(nf);
    const float2* ef2 = reinterpret_cast<const float2*>(ef);
    float2* im2 = reinterpret_cast<float2*>(g_im);
    float2* h2  = reinterpret_cast<float2*>(g_h);

    int lane = tid & 31;
    int wpb  = blockDim.x >> 5;
    for (int n = blockIdx.x * wpb + (tid >> 5); n < N; n += gridDim.x * wpb) {
        // node linear: p = nf cols {2l, 2l+1}
        float2 p = nf2[(size_t)n * D2 + lane];
        float ax = 0.f, ay = 0.f;
        #pragma unroll
        for (int k = 0; k < 32; k++) {
            float vx = __shfl_sync(0xffffffffu, p.x, k);   // nf[2k]
            float vy = __shfl_sync(0xffffffffu, p.y, k);   // nf[2k+1]
            float2 w0 = Wns[2 * k][lane];
            float2 w1 = Wns[2 * k + 1][lane];
            ax = fmaf(vx, w0.x, fmaf(vy, w1.x, ax));
            ay = fmaf(vx, w0.y, fmaf(vy, w1.y, ay));
        }
        // pulled raw edge-feature sum (lanes 0..7 hold float2 of ef)
        int start = g_rptr[n];
        int dg    = g_deg[n];
        int end   = start + dg;
        float2 fs = make_float2(0.f, 0.f);
        if (lane < FE2) {
            int i = start;
            for (; i + 3 < end; i += 4) {
                int e0 = g_ceid[i],     e1 = g_ceid[i + 1];
                int e2 = g_ceid[i + 2], e3 = g_ceid[i + 3];
                float2 v0 = __ldg(&ef2[(size_t)e0 * FE2 + lane]);
                float2 v1 = __ldg(&ef2[(size_t)e1 * FE2 + lane]);
                float2 v2 = __ldg(&ef2[(size_t)e2 * FE2 + lane]);
                float2 v3 = __ldg(&ef2[(size_t)e3 * FE2 + lane]);
                fs.x += (v0.x + v1.x) + (v2.x + v3.x);
                fs.y += (v0.y + v1.y) + (v2.y + v3.y);
            }
            for (; i < end; i++) {
                float2 v = __ldg(&ef2[(size_t)g_ceid[i] * FE2 + lane]);
                fs.x += v.x;
                fs.y += v.y;
            }
        }
        #pragma unroll
        for (int k = 0; k < FE2; k++) {
            float vx = __shfl_sync(0xffffffffu, fs.x, k);  // efsum[2k]
            float vy = __shfl_sync(0xffffffffu, fs.y, k);  // efsum[2k+1]
            float2 w0 = Wes[2 * k][lane];
            float2 w1 = Wes[2 * k + 1][lane];
            ax = fmaf(vx, w0.x, fmaf(vy, w1.x, ax));
            ay = fmaf(vx, w0.y, fmaf(vy, w1.y, ay));
        }
        float fd = (float)dg;
        float2 bnv = bns[lane], bev = bes[lane];
        float2 im = make_float2(ax + bnv.x + fd * bev.x,
                                ay + bnv.y + fd * bev.y);
        size_t o = (size_t)n * D2 + lane;
        im2[o] = im;
        h2[o]  = make_float2(fmaxf(im.x, 0.f), fmaxf(im.y, 0.f));
    }
}

// ------- C: mean-field level (float2 gather + combine) -----------------------
__global__ void k_level(const float* __restrict__ W,   // [64][64]
                        const float* __restrict__ b,   // [64]
                        int dir, int N) {
    __shared__ float2 Ws[D][D2];
    __shared__ float2 bs[D2];
    int tid = threadIdx.x;
    for (int i = tid; i < D * D2; i += blockDim.x)
        Ws[i / D2][i % D2] = reinterpret_cast<const float2*>(W)[i];
    if (tid < D2) bs[tid] = reinterpret_cast<const float2*>(b)[tid];
    __syncthreads();

    const float2* hin  = reinterpret_cast<const float2*>(dir ? g_hb : g_h);
    float2*       hout = reinterpret_cast<float2*>(dir ? g_h : g_hb);
    const float2* im2  = reinterpret_cast<const float2*>(g_im);

    int lane = tid & 31;
    int wpb  = blockDim.x >> 5;
    for (int n = blockIdx.x * wpb + (tid >> 5); n < N; n += gridDim.x * wpb) {
        int start = g_rptr[n];
        int end   = start + g_deg[n];
        float px = 0.f, py = 0.f;
        int i = start;
        for (; i + 3 < end; i += 4) {
            int s0 = g_csrc[i],     s1 = g_csrc[i + 1];
            int s2 = g_csrc[i + 2], s3 = g_csrc[i + 3];
            float2 v0 = __ldg(&hin[(size_t)s0 * D2 + lane]);
            float2 v1 = __ldg(&hin[(size_t)s1 * D2 + lane]);
            float2 v2 = __ldg(&hin[(size_t)s2 * D2 + lane]);
            float2 v3 = __ldg(&hin[(size_t)s3 * D2 + lane]);
            px += (v0.x + v1.x) + (v2.x + v3.x);
            py += (v0.y + v1.y) + (v2.y + v3.y);
        }
        for (; i < end; i++) {
            float2 v = __ldg(&hin[(size_t)g_csrc[i] * D2 + lane]);
            px += v.x;
            py += v.y;
        }
        size_t o = (size_t)n * D2 + lane;
        float2 im = im2[o];                  // hoisted: overlaps GEMV
        float ax = 0.f, ay = 0.f;
        #pragma unroll
        for (int k = 0; k < 32; k++) {
            float vx = __shfl_sync(0xffffffffu, px, k);   // pool[2k]
            float vy = __shfl_sync(0xffffffffu, py, k);   // pool[2k+1]
            float2 w0 = Ws[2 * k][lane];
            float2 w1 = Ws[2 * k + 1][lane];
            ax = fmaf(vx, w0.x, fmaf(vy, w1.x, ax));
            ay = fmaf(vx, w0.y, fmaf(vy, w1.y, ay));
        }
        float2 bv = bs[lane];
        hout[o] = make_float2(fmaxf(ax + bv.x + im.x, 0.f),
                              fmaxf(ay + bv.y + im.y, 0.f));
    }
}

// ------- D: final level fused: gather + combine + projection + graph pool ----
__global__ void k_level_final(const float* __restrict__ Wc,
                              const float* __restrict__ bc,
                              const float* __restrict__ Wf,
                              const float* __restrict__ bf,
                              const int*   __restrict__ gid,
                              float*       __restrict__ out,  // [G][64]
                              int dir, int N) {
    __shared__ float2 Wcs[D][D2];
    __shared__ float2 Wfs[D][D2];
    __shared__ float2 bcs[D2], bfs[D2];
    int tid = threadIdx.x;
    for (int i = tid; i < D * D2; i += blockDim.x) {
        Wcs[i / D2][i % D2] = reinterpret_cast<const float2*>(Wc)[i];
        Wfs[i / D2][i % D2] = reinterpret_cast<const float2*>(Wf)[i];
    }
    if (tid < D2) {
        bcs[tid] = reinterpret_cast<const float2*>(bc)[tid];
        bfs[tid] = reinterpret_cast<const float2*>(bf)[tid];
    }
    __syncthreads();

    const float2* hin = reinterpret_cast<const float2*>(dir ? g_hb : g_h);
    const float2* im2 = reinterpret_cast<const float2*>(g_im);

    int lane = tid & 31;
    int wpb  = blockDim.x >> 5;
    for (int n = blockIdx.x * wpb + (tid >> 5); n < N; n += gridDim.x * wpb) {
        int start = g_rptr[n];
        int end   = start + g_deg[n];
        float px = 0.f, py = 0.f;
        int i = start;
        for (; i + 3 < end; i += 4) {
            int s0 = g_csrc[i],     s1 = g_csrc[i + 1];
            int s2 = g_csrc[i + 2], s3 = g_csrc[i + 3];
            float2 v0 = __ldg(&hin[(size_t)s0 * D2 + lane]);
            float2 v1 = __ldg(&hin[(size_t)s1 * D2 + lane]);
            float2 v2 = __ldg(&hin[(size_t)s2 * D2 + lane]);
            float2 v3 = __ldg(&hin[(size_t)s3 * D2 + lane]);
            px += (v0.x + v1.x) + (v2.x + v3.x);
            py += (v0.y + v1.y) + (v2.y + v3.y);
        }
        for (; i < end; i++) {
            float2 v = __ldg(&hin[(size_t)g_csrc[i] * D2 + lane]);
            px += v.x;
            py += v.y;
        }
        size_t o = (size_t)n * D2 + lane;
        float2 im = im2[o];
        int g = gid[n];
        float ax = 0.f, ay = 0.f;
        #pragma unroll
        for (int k = 0; k < 32; k++) {
            float vx = __shfl_sync(0xffffffffu, px, k);
            float vy = __shfl_sync(0xffffffffu, py, k);
            float2 w0 = Wcs[2 * k][lane];
            float2 w1 = Wcs[2 * k + 1][lane];
            ax = fmaf(vx, w0.x, fmaf(vy, w1.x, ax));
            ay = fmaf(vx, w0.y, fmaf(vy, w1.y, ay));
        }
        float2 bcv = bcs[lane];
        float hx = fmaxf(ax + bcv.x + im.x, 0.f);
        float hy = fmaxf(ay + bcv.y + im.y, 0.f);
        // final projection, h stays in registers
        float fx = 0.f, fy = 0.f;
        #pragma unroll
        for (int k = 0; k < 32; k++) {
            float vx = __shfl_sync(0xffffffffu, hx, k);   // h[2k]
            float vy = __shfl_sync(0xffffffffu, hy, k);   // h[2k+1]
            float2 w0 = Wfs[2 * k][lane];
            float2 w1 = Wfs[2 * k + 1][lane];
            fx = fmaf(vx, w0.x, fmaf(vy, w1.x, fx));
            fy = fmaf(vx, w0.y, fmaf(vy, w1.y, fy));
        }
        float2 bfv = bfs[lane];
        float ox = fmaxf(fx + bfv.x, 0.f);
        float oy = fmaxf(fy + bfv.y, 0.f);
        atomicAdd(&out[(size_t)g * D + 2 * lane],     ox);
        atomicAdd(&out[(size_t)g * D + 2 * lane + 1], oy);
    }
}

// ------------------------------------------------------------------------ host
extern "C" void kernel_launch(void* const* d_in, const int* in_sizes, int n_in,
                              void* d_out, int out_size) {
    bool dict = (in_sizes[2] == in_sizes[3]);
    int iNF = 0, iEF = 1, iSRC, iDST, iGID, iWn, ibn, iWe, ibe, iWc, ibc, iWf, ibf;
    if (dict) { iSRC = 2; iDST = 3; iGID = 4; iWn = 5; ibn = 6; iWe = 7; ibe = 8;
                iWc = 9; ibc = 10; iWf = 11; ibf = 12; }
    else      { iWn = 2; ibn = 3; iWe = 4; ibe = 5; iWc = 6; ibc = 7; iWf = 8;
                ibf = 9; iSRC = 10; iDST = 11; iGID = 12; }

    const float* nf   = (const float*)d_in[iNF];
    const float* ef   = (const float*)d_in[iEF];
    const int*   esrc = (const int*)  d_in[iSRC];
    const int*   edst = (const int*)  d_in[iDST];
    const int*   gid  = (const int*)  d_in[iGID];
    const float* Wn   = (const float*)d_in[iWn];
    const float* bn   = (const float*)d_in[ibn];
    const float* We   = (const float*)d_in[iWe];
    const float* be   = (const float*)d_in[ibe];
    const float* Wc   = (const float*)d_in[iWc];
    const float* bc   = (const float*)d_in[ibc];
    const float* Wf   = (const float*)d_in[iWf];
    const float* bf   = (const float*)d_in[ibf];
    float* out = (float*)d_out;

    int N  = in_sizes[iGID];
    int E  = in_sizes[iSRC];
    int LV = in_sizes[iWc] / (D * D);

    const int THR = 256;
    int nb  = (N + THR - 1) / THR;
    int ebk = (E + THR - 1) / THR;
    int nsb = (N + SCAN_B - 1) / SCAN_B;
    const int GSB = 1184;

    k_zero_deg<<<nb, THR>>>(N);
    k_hist<<<ebk, THR>>>(edst, E);
    k_scanA<<<nsb, SCAN_B>>>(N);
    k_scanB<<<1, 256>>>(nsb);
    k_scanC<<<nb, THR>>>(N);
    k_fill<<<ebk, THR>>>(esrc, edst, E);

    k_input<<<GSB, THR>>>(nf, ef, Wn, bn, We, be, N);

    int dir = 0;
    for (int lv = 0; lv < LV - 1; lv++) {
        k_level<<<GSB, THR>>>(Wc + (size_t)lv * D * D, bc + (size_t)lv * D, dir, N);
        dir ^= 1;
    }

    k_zero_out<<<(out_size + THR - 1) / THR, THR>>>(out, out_size);
    k_level_final<<<GSB, THR>>>(Wc + (size_t)(LV - 1) * D * D,
                                bc + (size_t)(LV - 1) * D,
                                Wf, bf, gid, out, dir, N);
}

// round 13
// speedup vs baseline: 1.0435x; 1.0364x over previous
#include <cuda_runtime.h>
#include <cstdint>

// EmbedMeanField (structure2vec) for GB300 — CSR "pull", float2 datapath.
// N=50000, E=800000, G=128, FN=64, FE=16, D=64, LV=3.
// R9: 301.1us. R10/R11 float2: 299.0us (NEUTRAL -> not LDG-count-bound).
// R12/R13 theory: fixed grid 1184 > resident capacity (~5 blk/SM at ~48 regs)
// caused 2-wave execution of every heavy kernel. Fix: occupancy-sized
// single-wave grids (148 * maxActiveBlocksPerSM), grid-stride absorbs rest.

#define D    64
#define D2   32
#define FE   16
#define FE2  8
#define MAXN 50000
#define MAXE 800000
#define SCAN_B 512
#define NSM  148

__device__ __align__(256) float g_im [(size_t)MAXN * D];
__device__ __align__(256) float g_h  [(size_t)MAXN * D];
__device__ __align__(256) float g_hb [(size_t)MAXN * D];
__device__ int g_deg   [MAXN];
__device__ int g_rptr  [MAXN];
__device__ int g_cursor[MAXN];
__device__ int g_blk   [256];
__device__ int g_csrc  [MAXE];
__device__ int g_ceid  [MAXE];

// ------------------------------------------------------------- CSR build
__global__ void k_zero_deg(int N) {
    int i = blockIdx.x * blockDim.x + threadIdx.x;
    if (i < N) g_deg[i] = 0;
}
__global__ void k_hist(const int* __restrict__ edst, int E) {
    int e = blockIdx.x * blockDim.x + threadIdx.x;
    if (e < E) atomicAdd(&g_deg[edst[e]], 1);
}
__global__ void k_scanA(int N) {
    __shared__ int s[SCAN_B];
    int i = blockIdx.x * SCAN_B + threadIdx.x;
    int v = (i < N) ? g_deg[i] : 0;
    s[threadIdx.x] = v;
    __syncthreads();
    #pragma unroll
    for (int off = 1; off < SCAN_B; off <<= 1) {
        int t = (threadIdx.x >= off) ? s[threadIdx.x - off] : 0;
        __syncthreads();
        s[threadIdx.x] += t;
        __syncthreads();
    }
    if (i < N) g_rptr[i] = s[threadIdx.x] - v;
    if (threadIdx.x == SCAN_B - 1) g_blk[blockIdx.x] = s[SCAN_B - 1];
}
__global__ void k_scanB(int nb) {
    __shared__ int s[256];
    int t = threadIdx.x;
    int v = (t < nb) ? g_blk[t] : 0;
    s[t] = v;
    __syncthreads();
    #pragma unroll
    for (int off = 1; off < 256; off <<= 1) {
        int u = (t >= off) ? s[t - off] : 0;
        __syncthreads();
        s[t] += u;
        __syncthreads();
    }
    if (t < nb) g_blk[t] = s[t] - v;   // exclusive
}
__global__ void k_scanC(int N) {
    int i = blockIdx.x * blockDim.x + threadIdx.x;
    if (i < N) {
        int v = g_rptr[i] + g_blk[i / SCAN_B];
        g_rptr[i]   = v;
        g_cursor[i] = v;
    }
}
__global__ void k_fill(const int* __restrict__ esrc,
                       const int* __restrict__ edst, int E) {
    int e = blockIdx.x * blockDim.x + threadIdx.x;
    if (e < E) {
        int d = edst[e];
        int p = atomicAdd(&g_cursor[d], 1);
        g_csrc[p] = esrc[e];
        g_ceid[p] = e;
    }
}
__global__ void k_zero_out(float* __restrict__ p, int n) {
    int i = blockIdx.x * blockDim.x + threadIdx.x;
    if (i < n) p[i] = 0.f;
}

// ------- B: fused input layer (float2 datapath) ------------------------------
__global__ void k_input(const float* __restrict__ nf,  // [N][64]
                        const float* __restrict__ ef,  // [E][16]
                        const float* __restrict__ Wn,  // [64][64]
                        const float* __restrict__ bn,  // [64]
                        const float* __restrict__ We,  // [16][64]
                        const float* __restrict__ be,  // [64]
                        int N) {
    __shared__ float2 Wns[D][D2];      // Wns[r][c] = {Wn[r][2c], Wn[r][2c+1]}
    __shared__ float2 Wes[FE][D2];
    __shared__ float2 bns[D2], bes[D2];
    int tid = threadIdx.x;
    for (int i = tid; i < D * D2; i += blockDim.x)
        Wns[i / D2][i % D2] = reinterpret_cast<const float2*>(Wn)[i];
    for (int i = tid; i < FE * D2; i += blockDim.x)
        Wes[i / D2][i % D2] = reinterpret_cast<const float2*>(We)[i];
    if (tid < D2) {
        bns[tid] = reinterpret_cast<const float2*>(bn)[tid];
        bes[tid] = reinterpret_cast<const float2*>(be)[tid];
    }
    __syncthreads();

    const float2* nf2 = reinterpret_cast<const float2*>(nf);
    const float2* ef2 = reinterpret_cast<const float2*>(ef);
    float2* im2 = reinterpret_cast<float2*>(g_im);
    float2* h2  = reinterpret_cast<float2*>(g_h);

    int lane = tid & 31;
    int wpb  = blockDim.x >> 5;
    for (int n = blockIdx.x * wpb + (tid >> 5); n < N; n += gridDim.x * wpb) {
        float2 p = nf2[(size_t)n * D2 + lane];
        float ax = 0.f, ay = 0.f;
        #pragma unroll
        for (int k = 0; k < 32; k++) {
            float vx = __shfl_sync(0xffffffffu, p.x, k);   // nf[2k]
            float vy = __shfl_sync(0xffffffffu, p.y, k);   // nf[2k+1]
            float2 w0 = Wns[2 * k][lane];
            float2 w1 = Wns[2 * k + 1][lane];
            ax = fmaf(vx, w0.x, fmaf(vy, w1.x, ax));
            ay = fmaf(vx, w0.y, fmaf(vy, w1.y, ay));
        }
        int start = g_rptr[n];
        int dg    = g_deg[n];
        int end   = start + dg;
        float2 fs = make_float2(0.f, 0.f);
        if (lane < FE2) {
            int i = start;
            for (; i + 3 < end; i += 4) {
                int e0 = g_ceid[i],     e1 = g_ceid[i + 1];
                int e2 = g_ceid[i + 2], e3 = g_ceid[i + 3];
                float2 v0 = __ldg(&ef2[(size_t)e0 * FE2 + lane]);
                float2 v1 = __ldg(&ef2[(size_t)e1 * FE2 + lane]);
                float2 v2 = __ldg(&ef2[(size_t)e2 * FE2 + lane]);
                float2 v3 = __ldg(&ef2[(size_t)e3 * FE2 + lane]);
                fs.x += (v0.x + v1.x) + (v2.x + v3.x);
                fs.y += (v0.y + v1.y) + (v2.y + v3.y);
            }
            for (; i < end; i++) {
                float2 v = __ldg(&ef2[(size_t)g_ceid[i] * FE2 + lane]);
                fs.x += v.x;
                fs.y += v.y;
            }
        }
        #pragma unroll
        for (int k = 0; k < FE2; k++) {
            float vx = __shfl_sync(0xffffffffu, fs.x, k);
            float vy = __shfl_sync(0xffffffffu, fs.y, k);
            float2 w0 = Wes[2 * k][lane];
            float2 w1 = Wes[2 * k + 1][lane];
            ax = fmaf(vx, w0.x, fmaf(vy, w1.x, ax));
            ay = fmaf(vx, w0.y, fmaf(vy, w1.y, ay));
        }
        float fd = (float)dg;
        float2 bnv = bns[lane], bev = bes[lane];
        float2 im = make_float2(ax + bnv.x + fd * bev.x,
                                ay + bnv.y + fd * bev.y);
        size_t o = (size_t)n * D2 + lane;
        im2[o] = im;
        h2[o]  = make_float2(fmaxf(im.x, 0.f), fmaxf(im.y, 0.f));
    }
}

// ------- C: mean-field level (float2 gather + combine) -----------------------
__global__ void k_level(const float* __restrict__ W,
                        const float* __restrict__ b,
                        int dir, int N) {
    __shared__ float2 Ws[D][D2];
    __shared__ float2 bs[D2];
    int tid = threadIdx.x;
    for (int i = tid; i < D * D2; i += blockDim.x)
        Ws[i / D2][i % D2] = reinterpret_cast<const float2*>(W)[i];
    if (tid < D2) bs[tid] = reinterpret_cast<const float2*>(b)[tid];
    __syncthreads();

    const float2* hin  = reinterpret_cast<const float2*>(dir ? g_hb : g_h);
    float2*       hout = reinterpret_cast<float2*>(dir ? g_h : g_hb);
    const float2* im2  = reinterpret_cast<const float2*>(g_im);

    int lane = tid & 31;
    int wpb  = blockDim.x >> 5;
    for (int n = blockIdx.x * wpb + (tid >> 5); n < N; n += gridDim.x * wpb) {
        int start = g_rptr[n];
        int end   = start + g_deg[n];
        float px = 0.f, py = 0.f;
        int i = start;
        for (; i + 3 < end; i += 4) {
            int s0 = g_csrc[i],     s1 = g_csrc[i + 1];
            int s2 = g_csrc[i + 2], s3 = g_csrc[i + 3];
            float2 v0 = __ldg(&hin[(size_t)s0 * D2 + lane]);
            float2 v1 = __ldg(&hin[(size_t)s1 * D2 + lane]);
            float2 v2 = __ldg(&hin[(size_t)s2 * D2 + lane]);
            float2 v3 = __ldg(&hin[(size_t)s3 * D2 + lane]);
            px += (v0.x + v1.x) + (v2.x + v3.x);
            py += (v0.y + v1.y) + (v2.y + v3.y);
        }
        for (; i < end; i++) {
            float2 v = __ldg(&hin[(size_t)g_csrc[i] * D2 + lane]);
            px += v.x;
            py += v.y;
        }
        size_t o = (size_t)n * D2 + lane;
        float2 im = im2[o];                  // hoisted: overlaps GEMV
        float ax = 0.f, ay = 0.f;
        #pragma unroll
        for (int k = 0; k < 32; k++) {
            float vx = __shfl_sync(0xffffffffu, px, k);
            float vy = __shfl_sync(0xffffffffu, py, k);
            float2 w0 = Ws[2 * k][lane];
            float2 w1 = Ws[2 * k + 1][lane];
            ax = fmaf(vx, w0.x, fmaf(vy, w1.x, ax));
            ay = fmaf(vx, w0.y, fmaf(vy, w1.y, ay));
        }
        float2 bv = bs[lane];
        hout[o] = make_float2(fmaxf(ax + bv.x + im.x, 0.f),
                              fmaxf(ay + bv.y + im.y, 0.f));
    }
}

// ------- D: final level fused: gather + combine + projection + graph pool ----
__global__ void k_level_final(const float* __restrict__ Wc,
                              const float* __restrict__ bc,
                              const float* __restrict__ Wf,
                              const float* __restrict__ bf,
                              const int*   __restrict__ gid,
                              float*       __restrict__ out,  // [G][64]
                              int dir, int N) {
    __shared__ float2 Wcs[D][D2];
    __shared__ float2 Wfs[D][D2];
    __shared__ float2 bcs[D2], bfs[D2];
    int tid = threadIdx.x;
    for (int i = tid; i < D * D2; i += blockDim.x) {
        Wcs[i / D2][i % D2] = reinterpret_cast<const float2*>(Wc)[i];
        Wfs[i / D2][i % D2] = reinterpret_cast<const float2*>(Wf)[i];
    }
    if (tid < D2) {
        bcs[tid] = reinterpret_cast<const float2*>(bc)[tid];
        bfs[tid] = reinterpret_cast<const float2*>(bf)[tid];
    }
    __syncthreads();

    const float2* hin = reinterpret_cast<const float2*>(dir ? g_hb : g_h);
    const float2* im2 = reinterpret_cast<const float2*>(g_im);

    int lane = tid & 31;
    int wpb  = blockDim.x >> 5;
    for (int n = blockIdx.x * wpb + (tid >> 5); n < N; n += gridDim.x * wpb) {
        int start = g_rptr[n];
        int end   = start + g_deg[n];
        float px = 0.f, py = 0.f;
        int i = start;
        for (; i + 3 < end; i += 4) {
            int s0 = g_csrc[i],     s1 = g_csrc[i + 1];
            int s2 = g_csrc[i + 2], s3 = g_csrc[i + 3];
            float2 v0 = __ldg(&hin[(size_t)s0 * D2 + lane]);
            float2 v1 = __ldg(&hin[(size_t)s1 * D2 + lane]);
            float2 v2 = __ldg(&hin[(size_t)s2 * D2 + lane]);
            float2 v3 = __ldg(&hin[(size_t)s3 * D2 + lane]);
            px += (v0.x + v1.x) + (v2.x + v3.x);
            py += (v0.y + v1.y) + (v2.y + v3.y);
        }
        for (; i < end; i++) {
            float2 v = __ldg(&hin[(size_t)g_csrc[i] * D2 + lane]);
            px += v.x;
            py += v.y;
        }
        size_t o = (size_t)n * D2 + lane;
        float2 im = im2[o];
        int g = gid[n];
        float ax = 0.f, ay = 0.f;
        #pragma unroll
        for (int k = 0; k < 32; k++) {
            float vx = __shfl_sync(0xffffffffu, px, k);
            float vy = __shfl_sync(0xffffffffu, py, k);
            float2 w0 = Wcs[2 * k][lane];
            float2 w1 = Wcs[2 * k + 1][lane];
            ax = fmaf(vx, w0.x, fmaf(vy, w1.x, ax));
            ay = fmaf(vx, w0.y, fmaf(vy, w1.y, ay));
        }
        float2 bcv = bcs[lane];
        float hx = fmaxf(ax + bcv.x + im.x, 0.f);
        float hy = fmaxf(ay + bcv.y + im.y, 0.f);
        float fx = 0.f, fy = 0.f;
        #pragma unroll
        for (int k = 0; k < 32; k++) {
            float vx = __shfl_sync(0xffffffffu, hx, k);
            float vy = __shfl_sync(0xffffffffu, hy, k);
            float2 w0 = Wfs[2 * k][lane];
            float2 w1 = Wfs[2 * k + 1][lane];
            fx = fmaf(vx, w0.x, fmaf(vy, w1.x, fx));
            fy = fmaf(vx, w0.y, fmaf(vy, w1.y, fy));
        }
        float2 bfv = bfs[lane];
        float ox = fmaxf(fx + bfv.x, 0.f);
        float oy = fmaxf(fy + bfv.y, 0.f);
        atomicAdd(&out[(size_t)g * D + 2 * lane],     ox);
        atomicAdd(&out[(size_t)g * D + 2 * lane + 1], oy);
    }
}

// ------------------------------------------------------------------------ host
static inline int single_wave_grid(const void* func, int thr, size_t smem) {
    int per_sm = 0;
    cudaError_t err = cudaOccupancyMaxActiveBlocksPerMultiprocessor(
        &per_sm, func, thr, smem);
    if (err != cudaSuccess || per_sm < 1) per_sm = 4;  // safe fallback
    return NSM * per_sm;   // exactly one full-occupancy wave
}

extern "C" void kernel_launch(void* const* d_in, const int* in_sizes, int n_in,
                              void* d_out, int out_size) {
    bool dict = (in_sizes[2] == in_sizes[3]);
    int iNF = 0, iEF = 1, iSRC, iDST, iGID, iWn, ibn, iWe, ibe, iWc, ibc, iWf, ibf;
    if (dict) { iSRC = 2; iDST = 3; iGID = 4; iWn = 5; ibn = 6; iWe = 7; ibe = 8;
                iWc = 9; ibc = 10; iWf = 11; ibf = 12; }
    else      { iWn = 2; ibn = 3; iWe = 4; ibe = 5; iWc = 6; ibc = 7; iWf = 8;
                ibf = 9; iSRC = 10; iDST = 11; iGID = 12; }

    const float* nf   = (const float*)d_in[iNF];
    const float* ef   = (const float*)d_in[iEF];
    const int*   esrc = (const int*)  d_in[iSRC];
    const int*   edst = (const int*)  d_in[iDST];
    const int*   gid  = (const int*)  d_in[iGID];
    const float* Wn   = (const float*)d_in[iWn];
    const float* bn   = (const float*)d_in[ibn];
    const float* We   = (const float*)d_in[iWe];
    const float* be   = (const float*)d_in[ibe];
    const float* Wc   = (const float*)d_in[iWc];
    const float* bc   = (const float*)d_in[ibc];
    const float* Wf   = (const float*)d_in[iWf];
    const float* bf   = (const float*)d_in[ibf];
    float* out = (float*)d_out;

    int N  = in_sizes[iGID];
    int E  = in_sizes[iSRC];
    int LV = in_sizes[iWc] / (D * D);

    const int THR = 256;
    int nb  = (N + THR - 1) / THR;
    int ebk = (E + THR - 1) / THR;
    int nsb = (N + SCAN_B - 1) / SCAN_B;

    // occupancy-sized single-wave grids for the heavy kernels
    int g_in  = single_wave_grid((const void*)k_input,       THR, 0);
    int g_lv  = single_wave_grid((const void*)k_level,       THR, 0);
    int g_fin = single_wave_grid((const void*)k_level_final, THR, 0);

    k_zero_deg<<<nb, THR>>>(N);
    k_hist<<<ebk, THR>>>(edst, E);
    k_scanA<<<nsb, SCAN_B>>>(N);
    k_scanB<<<1, 256>>>(nsb);
    k_scanC<<<nb, THR>>>(N);
    k_fill<<<ebk, THR>>>(esrc, edst, E);

    k_input<<<g_in, THR>>>(nf, ef, Wn, bn, We, be, N);

    int dir = 0;
    for (int lv = 0; lv < LV - 1; lv++) {
        k_level<<<g_lv, THR>>>(Wc + (size_t)lv * D * D, bc + (size_t)lv * D, dir, N);
        dir ^= 1;
    }

    k_zero_out<<<(out_size + THR - 1) / THR, THR>>>(out, out_size);
    k_level_final<<<g_fin, THR>>>(Wc + (size_t)(LV - 1) * D * D,
                                  bc + (size_t)(LV - 1) * D,
                                  Wf, bf, gid, out, dir, N);
}